// round 13
// baseline (speedup 1.0000x reference)
#include <cuda_runtime.h>
#include <cuda_fp16.h>
#include <cstdint>

// ---------------------------------------------------------------------------
// QuantLinear, fp16 mma.sync path (base sm_103 target — tcgen05 unavailable).
//   out[8192,11008] = x[8192,4096] @ dequant(W)[4096,11008] + bias
// Pre-pass: x fp32 -> fp16 scratch, k-permuted within 8-groups to match the
// nibble-pair dequant order [v0,v4,v1,v5,v2,v6,v3,v7].
// Main: R12 skeleton (128x128x64 tile, 4 warps, 64x64 warp tiles, 2 CTA/SM,
// 3-stage A ring, one sync/tile) + qweight staged via cp.async smem ring
// (frees regs) + software-pipelined fragments in compute_tile (A ping-pong,
// B halves) so every LDSM has >=16 MMA issues of slack.
// ---------------------------------------------------------------------------

namespace {
constexpr int kInF  = 4096;
constexpr int kOutF = 11008;
constexpr int kM    = 8192;

constexpr int BM = 128;
constexpr int BN = 128;
constexpr int BK = 64;
constexpr int NT = kInF / BK;        // 64 k-tiles

constexpr int RSTR  = 144;           // smem row stride bytes (128B data + 16 pad)
constexpr int STAGE = 128 * RSTR;    // 18432 B per tile stage (A or B)
constexpr int S_A   = 0;             // A: 3 stages
constexpr int S_B   = 3 * STAGE;     // B: 2 stages
constexpr int S_Q   = 5 * STAGE;     // Q: 4 stages x 4096 B
constexpr int Q_STG = 4096;
constexpr int SMEM_TOTAL = S_Q + 4 * Q_STG;  // 108544 B (2 CTA/SM: 217088)
}  // namespace

// 67 MB fp16 scratch for converted x (static __device__: no runtime alloc)
__device__ __align__(128) __half g_x16[(size_t)kM * kInF];

// ---------------------------------------------------------------------------
__device__ __forceinline__ uint32_t smem_u32(const void* p) {
    uint32_t a;
    asm("{ .reg .u64 t; cvta.to.shared.u64 t, %1; cvt.u32.u64 %0, t; }"
        : "=r"(a) : "l"(p));
    return a;
}

#define LDSM_X4(r0, r1, r2, r3, addr)                                          \
    asm volatile("ldmatrix.sync.aligned.m8n8.x4.shared.b16 {%0,%1,%2,%3}, [%4];" \
                 : "=r"(r0), "=r"(r1), "=r"(r2), "=r"(r3) : "r"(addr))

#define MMA16816(d, a, b0, b1)                                                \
    asm volatile(                                                             \
        "mma.sync.aligned.m16n8k16.row.col.f32.f16.f16.f32 "                  \
        "{%0,%1,%2,%3}, {%4,%5,%6,%7}, {%8,%9}, {%0,%1,%2,%3};"               \
        : "+f"((d)[0]), "+f"((d)[1]), "+f"((d)[2]), "+f"((d)[3])              \
        : "r"((a)[0]), "r"((a)[1]), "r"((a)[2]), "r"((a)[3]),                 \
          "r"(b0), "r"(b1))

#define CP_ASYNC16(dst, src)                                                  \
    asm volatile("cp.async.cg.shared.global [%0], [%1], 16;"                  \
                 :: "r"(dst), "l"(src))
#define CP_COMMIT() asm volatile("cp.async.commit_group;")
#define CP_WAIT1()  asm volatile("cp.async.wait_group 1;")

// ---------------------------------------------------------------------------
// Pre-pass: x fp32 -> fp16, permuted within each 8-k group to
// [v0,v4,v1,v5,v2,v6,v3,v7] (matches nibble-pair dequant output order).
// ---------------------------------------------------------------------------
__global__ void __launch_bounds__(256)
convert_x_kernel(const float* __restrict__ x) {
    size_t i = (size_t)blockIdx.x * blockDim.x + threadIdx.x;  // one per 8 floats
    constexpr size_t TOT = (size_t)kM * kInF / 8;
    if (i >= TOT) return;
    const float4* s = reinterpret_cast<const float4*>(x) + i * 2;
    float4 a = s[0], b = s[1];
    __half2 h0 = __floats2half2_rn(a.x, b.x);   // (v0, v4)
    __half2 h1 = __floats2half2_rn(a.y, b.y);   // (v1, v5)
    __half2 h2 = __floats2half2_rn(a.z, b.z);   // (v2, v6)
    __half2 h3 = __floats2half2_rn(a.w, b.w);   // (v3, v7)
    uint4 o;
    o.x = *reinterpret_cast<uint32_t*>(&h0);
    o.y = *reinterpret_cast<uint32_t*>(&h1);
    o.z = *reinterpret_cast<uint32_t*>(&h2);
    o.w = *reinterpret_cast<uint32_t*>(&h3);
    reinterpret_cast<uint4*>(g_x16)[i] = o;
}

// ---------------------------------------------------------------------------
// Main GEMM kernel: 128 threads, 4 warps (2x2), 64x64 warp tiles
// ---------------------------------------------------------------------------
__global__ void __launch_bounds__(128, 2)
qlinear_hmma_kernel(const float* __restrict__ scales,
                    const float* __restrict__ bias,
                    const int*   __restrict__ qweight,
                    const int*   __restrict__ qzeros,
                    float*       __restrict__ out)
{
    extern __shared__ char smem[];
    const uint32_t sb = smem_u32(smem);
    const int tid  = threadIdx.x;
    const int lane = tid & 31;
    const int wid  = tid >> 5;               // 0..3
    const int warp_m = (wid & 1) * 64;
    const int warp_n = (wid >> 1) * 64;
    const int m0 = blockIdx.y * BM;
    const int n0 = blockIdx.x * BN;
    const int n  = n0 + tid;                 // this thread's B column
    const int zshift = (n & 7) * 4;
    const size_t zcol = (size_t)(n >> 3);

    // -------- A tile cp.async issue (tile t -> stage s), no commit ---------
    auto issue_a = [&](int t, int s) {
#pragma unroll
        for (int j = 0; j < 8; ++j) {
            const int idx = j * 128 + tid;   // 1024 16B chunks
            const int row = idx >> 3;
            const int col = idx & 7;
            const uint32_t dst = sb + S_A + s * STAGE + row * RSTR + col * 16;
            const __half* src = g_x16 + (size_t)(m0 + row) * kInF + t * BK + col * 8;
            CP_ASYNC16(dst, src);
        }
    };

    // -------- Q tile cp.async: 8 rows x 512B -> smem ring, no commit --------
    auto issue_q = [&](int t, int qs) {
#pragma unroll
        for (int j = 0; j < 2; ++j) {
            const int c = tid * 2 + j;       // 256 16B chunks
            const int row = c >> 5;          // 0..7
            const int c16 = c & 31;
            const uint32_t dst = sb + S_Q + qs * Q_STG + c * 16;
            const int* src = qweight + (size_t)(t * 8 + row) * kOutF + n0 + c16 * 4;
            CP_ASYNC16(dst, src);
        }
    };

    // -------- scale/zero (updated at 128-k group boundaries) ----------------
    float sc = scales[n];
    int   z  = (qzeros[zcol] >> zshift) & 15;

    // -------- B dequant: read Q from smem ring -> dequant -> B stage --------
    auto sts_b = [&](int sB, int qs) {
        const uint32_t zbits = (0x6400u | (uint32_t)z) * 0x00010001u;
        const __half2 hz = *reinterpret_cast<const __half2*>(&zbits);
        const __half2 hs = __float2half2_rn(sc);
        const char* qp = smem + S_Q + qs * Q_STG + tid * 4;
        char* bp = smem + S_B + sB * STAGE + tid * RSTR;
#pragma unroll
        for (int i = 0; i < 8; ++i) {
            const uint32_t q = *reinterpret_cast<const uint32_t*>(qp + i * 512);
            uint32_t u0 = (q & 0x000F000Fu)         | 0x64006400u;
            uint32_t u1 = ((q >> 4) & 0x000F000Fu)  | 0x64006400u;
            uint32_t u2 = ((q >> 8) & 0x000F000Fu)  | 0x64006400u;
            uint32_t u3 = ((q >> 12) & 0x000F000Fu) | 0x64006400u;
            __half2 v0 = __hmul2(__hsub2(*reinterpret_cast<__half2*>(&u0), hz), hs);
            __half2 v1 = __hmul2(__hsub2(*reinterpret_cast<__half2*>(&u1), hz), hs);
            __half2 v2 = __hmul2(__hsub2(*reinterpret_cast<__half2*>(&u2), hz), hs);
            __half2 v3 = __hmul2(__hsub2(*reinterpret_cast<__half2*>(&u3), hz), hs);
            uint4 pk;
            pk.x = *reinterpret_cast<uint32_t*>(&v0);
            pk.y = *reinterpret_cast<uint32_t*>(&v1);
            pk.z = *reinterpret_cast<uint32_t*>(&v2);
            pk.w = *reinterpret_cast<uint32_t*>(&v3);
            *reinterpret_cast<uint4*>(bp + i * 16) = pk;
        }
    };

    // -------- accumulators --------------------------------------------------
    float acc[4][8][4];
#pragma unroll
    for (int mt = 0; mt < 4; ++mt)
#pragma unroll
        for (int nt = 0; nt < 8; ++nt)
#pragma unroll
            for (int r = 0; r < 4; ++r) acc[mt][nt][r] = 0.f;

    const uint32_t a_lane = (warp_m + (lane & 15)) * RSTR + (lane >> 4) * 16;
    const uint32_t b_lane = (warp_n + (lane & 7) + ((lane >> 4) << 3)) * RSTR
                          + ((lane >> 3) & 1) * 16;

    // -------- software-pipelined compute: A ping-pong, B in halves ----------
    auto compute_tile = [&](int sA, int sB) {
        const uint32_t abase = sb + S_A + sA * STAGE + a_lane;
        const uint32_t bbase = sb + S_B + sB * STAGE + b_lane;
        uint32_t af[2][4][4];
        uint32_t b0[2][4], b1[2][4];
        // preload k16=0: A + B half0 (nt2 = 0,1)
#pragma unroll
        for (int mt = 0; mt < 4; ++mt)
            LDSM_X4(af[0][mt][0], af[0][mt][1], af[0][mt][2], af[0][mt][3],
                    abase + mt * 16 * RSTR);
        LDSM_X4(b0[0][0], b0[0][1], b0[0][2], b0[0][3], bbase);
        LDSM_X4(b0[1][0], b0[1][1], b0[1][2], b0[1][3], bbase + 16 * RSTR);
#pragma unroll
        for (int k16 = 0; k16 < 4; ++k16) {
            const int cur = k16 & 1, nxt = cur ^ 1;
            // B half1 of current k16 (nt2 = 2,3)
            LDSM_X4(b1[0][0], b1[0][1], b1[0][2], b1[0][3],
                    bbase + 2 * 16 * RSTR + k16 * 32);
            LDSM_X4(b1[1][0], b1[1][1], b1[1][2], b1[1][3],
                    bbase + 3 * 16 * RSTR + k16 * 32);
            // MMAs on half0 (nt 0..3)
#pragma unroll
            for (int mt = 0; mt < 4; ++mt)
#pragma unroll
                for (int nt = 0; nt < 4; ++nt) {
                    const int h = (nt & 1) * 2;
                    MMA16816(acc[mt][nt], af[cur][mt], b0[nt >> 1][h], b0[nt >> 1][h + 1]);
                }
            // prefetch next k16: A + B half0
            if (k16 < 3) {
#pragma unroll
                for (int mt = 0; mt < 4; ++mt)
                    LDSM_X4(af[nxt][mt][0], af[nxt][mt][1], af[nxt][mt][2], af[nxt][mt][3],
                            abase + mt * 16 * RSTR + (k16 + 1) * 32);
                LDSM_X4(b0[0][0], b0[0][1], b0[0][2], b0[0][3],
                        bbase + (k16 + 1) * 32);
                LDSM_X4(b0[1][0], b0[1][1], b0[1][2], b0[1][3],
                        bbase + 16 * RSTR + (k16 + 1) * 32);
            }
            // MMAs on half1 (nt 4..7)
#pragma unroll
            for (int mt = 0; mt < 4; ++mt)
#pragma unroll
                for (int nt = 4; nt < 8; ++nt) {
                    const int h = (nt & 1) * 2;
                    MMA16816(acc[mt][nt], af[cur][mt],
                             b1[(nt >> 1) - 2][h], b1[(nt >> 1) - 2][h + 1]);
                }
        }
    };

    // -------- prologue ------------------------------------------------------
    // G0 = {A(0), Q(0), Q(1), Q(2)}; G1 = {A(1)}
    issue_a(0, 0);
    issue_q(0, 0); issue_q(1, 1); issue_q(2, 2);
    CP_COMMIT();
    issue_a(1, 1);
    CP_COMMIT();
    CP_WAIT1();                      // G0 done: A(0), Q(0..2)
    __syncthreads();                 // publish
    sts_b(0, 0);                     // B(0) from Q(0)
    __syncthreads();                 // publish B(0)

    // -------- main loop: one commit per iteration ---------------------------
    // invariant: iter t commits {A(t+2), Q(t+3)}; wait1 at iter t end
    // guarantees A(t+1) landed and Q(t+2) landed (published by this sync,
    // read at sts_b during iter t+1).
    int sA = 0;                      // t % 3
    for (int t = 0; t < NT; ++t) {
        const bool more = (t + 1 < NT);
        if (t + 2 < NT) {
            int s2 = sA + 2; if (s2 >= 3) s2 -= 3;
            issue_a(t + 2, s2);
        }
        if (t + 3 < NT) issue_q(t + 3, (t + 3) & 3);
        CP_COMMIT();
        // scale/zero for tile t+1 (group boundary only) — covered by compute
        if (more && (((t + 1) & 1) == 0)) {
            const int g = (t + 1) >> 1;
            sc = scales[(size_t)g * kOutF + n];
            z  = (qzeros[(size_t)g * (kOutF / 8) + zcol] >> zshift) & 15;
        }

        compute_tile(sA, t & 1);

        if (more) {
            CP_WAIT1();              // A(t+1), Q(t+2) landed
            sts_b((t + 1) & 1, (t + 1) & 3);   // Q(t+1) published last sync
            __syncthreads();
        }
        if (++sA == 3) sA = 0;
    }

    // -------- epilogue: +bias, fp32 stores ---------------------------------
    const int g  = lane >> 2;
    const int tg = lane & 3;
#pragma unroll
    for (int nt = 0; nt < 8; ++nt) {
        const int c = n0 + warp_n + nt * 8 + tg * 2;
        const float2 bv = *reinterpret_cast<const float2*>(bias + c);
#pragma unroll
        for (int mt = 0; mt < 4; ++mt) {
            const int r0 = m0 + warp_m + mt * 16 + g;
            float2 v0 = make_float2(acc[mt][nt][0] + bv.x, acc[mt][nt][1] + bv.y);
            float2 v1 = make_float2(acc[mt][nt][2] + bv.x, acc[mt][nt][3] + bv.y);
            *reinterpret_cast<float2*>(out + (size_t)r0 * kOutF + c)       = v0;
            *reinterpret_cast<float2*>(out + (size_t)(r0 + 8) * kOutF + c) = v1;
        }
    }
}

// ---------------------------------------------------------------------------
extern "C" void kernel_launch(void* const* d_in, const int* in_sizes, int n_in,
                              void* d_out, int out_size)
{
    (void)in_sizes; (void)n_in; (void)out_size;
    const float* x       = (const float*)d_in[0];
    const float* scales  = (const float*)d_in[1];
    const float* bias    = (const float*)d_in[2];
    const int*   qweight = (const int*)d_in[3];
    const int*   qzeros  = (const int*)d_in[4];
    float*       out     = (float*)d_out;

    const size_t tot8 = (size_t)kM * kInF / 8;
    convert_x_kernel<<<(unsigned)((tot8 + 255) / 256), 256>>>(x);

    cudaFuncSetAttribute(qlinear_hmma_kernel,
                         cudaFuncAttributeMaxDynamicSharedMemorySize, SMEM_TOTAL);
    dim3 grid(kOutF / BN, kM / BM);  // (86, 64)
    qlinear_hmma_kernel<<<grid, 128, SMEM_TOTAL>>>(scales, bias, qweight, qzeros, out);
}

// round 14
// speedup vs baseline: 1.1121x; 1.1121x over previous
#include <cuda_runtime.h>
#include <cuda_fp16.h>
#include <cstdint>

// ---------------------------------------------------------------------------
// QuantLinear, fp16 mma.sync path (base sm_103 target — tcgen05 unavailable).
//   out[8192,11008] = x[8192,4096] @ dequant(W)[4096,11008] + bias
// Pre-pass: x fp32 -> fp16 scratch, k-permuted within 8-groups to match the
// nibble-pair dequant order [v0,v4,v1,v5,v2,v6,v3,v7].
// Main: R12 skeleton (128x128x64 tile, 4 warps, 64x64 warp tiles, 2 CTA/SM,
// 3-stage cp.async A ring with wait_group 1, one sync per k-tile) with
// strength-reduced addressing (precomputed base pointers) and group-hoisted
// dequant constants. Compute loop byte-identical to R12.
// ---------------------------------------------------------------------------

namespace {
constexpr int kInF  = 4096;
constexpr int kOutF = 11008;
constexpr int kM    = 8192;

constexpr int BM = 128;
constexpr int BN = 128;
constexpr int BK = 64;
constexpr int NT = kInF / BK;        // 64 k-tiles

constexpr int RSTR  = 144;           // smem row stride in bytes (128B data + 16 pad)
constexpr int STAGE = 128 * RSTR;    // 18432 B per tile stage (A or B)
constexpr int S_A   = 0;             // A: 3 stages
constexpr int S_B   = 3 * STAGE;     // B: 2 stages
constexpr int SMEM_TOTAL = 5 * STAGE;  // 92160 B (2 CTA/SM)
}  // namespace

// 67 MB fp16 scratch for converted x (static __device__: no runtime alloc)
__device__ __align__(128) __half g_x16[(size_t)kM * kInF];

// ---------------------------------------------------------------------------
__device__ __forceinline__ uint32_t smem_u32(const void* p) {
    uint32_t a;
    asm("{ .reg .u64 t; cvta.to.shared.u64 t, %1; cvt.u32.u64 %0, t; }"
        : "=r"(a) : "l"(p));
    return a;
}

#define LDSM_X4(r0, r1, r2, r3, addr)                                          \
    asm volatile("ldmatrix.sync.aligned.m8n8.x4.shared.b16 {%0,%1,%2,%3}, [%4];" \
                 : "=r"(r0), "=r"(r1), "=r"(r2), "=r"(r3) : "r"(addr))

#define MMA16816(d, a, b0, b1)                                                \
    asm volatile(                                                             \
        "mma.sync.aligned.m16n8k16.row.col.f32.f16.f16.f32 "                  \
        "{%0,%1,%2,%3}, {%4,%5,%6,%7}, {%8,%9}, {%0,%1,%2,%3};"               \
        : "+f"((d)[0]), "+f"((d)[1]), "+f"((d)[2]), "+f"((d)[3])              \
        : "r"((a)[0]), "r"((a)[1]), "r"((a)[2]), "r"((a)[3]),                 \
          "r"(b0), "r"(b1))

#define CP_ASYNC16(dst, src)                                                  \
    asm volatile("cp.async.cg.shared.global [%0], [%1], 16;"                  \
                 :: "r"(dst), "l"(src))
#define CP_COMMIT() asm volatile("cp.async.commit_group;")
#define CP_WAIT1()  asm volatile("cp.async.wait_group 1;")

// ---------------------------------------------------------------------------
// Pre-pass: x fp32 -> fp16, permuted within each 8-k group to
// [v0,v4,v1,v5,v2,v6,v3,v7] (matches nibble-pair dequant output order).
// ---------------------------------------------------------------------------
__global__ void __launch_bounds__(256)
convert_x_kernel(const float* __restrict__ x) {
    size_t i = (size_t)blockIdx.x * blockDim.x + threadIdx.x;  // one per 8 floats
    constexpr size_t TOT = (size_t)kM * kInF / 8;
    if (i >= TOT) return;
    const float4* s = reinterpret_cast<const float4*>(x) + i * 2;
    float4 a = s[0], b = s[1];
    __half2 h0 = __floats2half2_rn(a.x, b.x);   // (v0, v4)
    __half2 h1 = __floats2half2_rn(a.y, b.y);   // (v1, v5)
    __half2 h2 = __floats2half2_rn(a.z, b.z);   // (v2, v6)
    __half2 h3 = __floats2half2_rn(a.w, b.w);   // (v3, v7)
    uint4 o;
    o.x = *reinterpret_cast<uint32_t*>(&h0);
    o.y = *reinterpret_cast<uint32_t*>(&h1);
    o.z = *reinterpret_cast<uint32_t*>(&h2);
    o.w = *reinterpret_cast<uint32_t*>(&h3);
    reinterpret_cast<uint4*>(g_x16)[i] = o;
}

// ---------------------------------------------------------------------------
// Main GEMM kernel: 128 threads, 4 warps (2x2), 64x64 warp tiles
// ---------------------------------------------------------------------------
__global__ void __launch_bounds__(128, 2)
qlinear_hmma_kernel(const float* __restrict__ scales,
                    const float* __restrict__ bias,
                    const int*   __restrict__ qweight,
                    const int*   __restrict__ qzeros,
                    float*       __restrict__ out)
{
    extern __shared__ char smem[];
    const uint32_t sb = smem_u32(smem);
    const int tid  = threadIdx.x;
    const int lane = tid & 31;
    const int wid  = tid >> 5;               // 0..3
    const int warp_m = (wid & 1) * 64;
    const int warp_n = (wid >> 1) * 64;
    const int m0 = blockIdx.y * BM;
    const int n0 = blockIdx.x * BN;
    const int n  = n0 + tid;                 // this thread's B column
    const int zshift = (n & 7) * 4;
    const size_t zcol = (size_t)(n >> 3);

    // -------- precomputed base pointers (strength reduction) ----------------
    // A chunk (j,tid): row = 16j + (tid>>3), col = tid&7 (fixed per thread)
    const __half* aP = g_x16 + (size_t)(m0 + (tid >> 3)) * kInF + (tid & 7) * 8;
    const uint32_t aDst = sb + S_A + (tid >> 3) * RSTR + (tid & 7) * 16;
    const int*   qP = qweight + n;

    // -------- A tile cp.async issue (tile t -> stage s), no commit ---------
    auto issue_a = [&](int t, int s) {
        const __half* src = aP + t * BK;
        const uint32_t dst = aDst + s * STAGE;
#pragma unroll
        for (int j = 0; j < 8; ++j)
            CP_ASYNC16(dst + j * (16 * RSTR), src + (size_t)j * (16 * kInF));
    };

    // -------- qweight staging; dequant constants at group boundaries -------
    uint32_t qw[8];
    __half2  hz, hs;
    {
        const float sc = scales[n];
        const int   z  = (qzeros[zcol] >> zshift) & 15;
        const uint32_t zbits = (0x6400u | (uint32_t)z) * 0x00010001u;
        hz = *reinterpret_cast<const __half2*>(&zbits);
        hs = __float2half2_rn(sc);
    }
    auto ldg_qw = [&](int t) {
        const int* qpt = qP + (size_t)(t * 8) * kOutF;
#pragma unroll
        for (int i = 0; i < 8; ++i) qw[i] = (uint32_t)qpt[(size_t)i * kOutF];
        if ((t & 1) == 0 && t > 0) {         // new 128-k group
            const int g = t >> 1;
            const float sc = scales[(size_t)g * kOutF + n];
            const int   z  = (qzeros[(size_t)g * (kOutF / 8) + zcol] >> zshift) & 15;
            const uint32_t zbits = (0x6400u | (uint32_t)z) * 0x00010001u;
            hz = *reinterpret_cast<const __half2*>(&zbits);
            hs = __float2half2_rn(sc);
        }
    };

    // -------- B dequant -> smem stage --------------------------------------
    char* const bP = smem + S_B + tid * RSTR;
    auto sts_b = [&](int s) {
        char* bp = bP + s * STAGE;
#pragma unroll
        for (int i = 0; i < 8; ++i) {
            const uint32_t q = qw[i];
            uint32_t u0 = (q & 0x000F000Fu)         | 0x64006400u;
            uint32_t u1 = ((q >> 4) & 0x000F000Fu)  | 0x64006400u;
            uint32_t u2 = ((q >> 8) & 0x000F000Fu)  | 0x64006400u;
            uint32_t u3 = ((q >> 12) & 0x000F000Fu) | 0x64006400u;
            __half2 v0 = __hmul2(__hsub2(*reinterpret_cast<__half2*>(&u0), hz), hs);
            __half2 v1 = __hmul2(__hsub2(*reinterpret_cast<__half2*>(&u1), hz), hs);
            __half2 v2 = __hmul2(__hsub2(*reinterpret_cast<__half2*>(&u2), hz), hs);
            __half2 v3 = __hmul2(__hsub2(*reinterpret_cast<__half2*>(&u3), hz), hs);
            uint4 pk;
            pk.x = *reinterpret_cast<uint32_t*>(&v0);
            pk.y = *reinterpret_cast<uint32_t*>(&v1);
            pk.z = *reinterpret_cast<uint32_t*>(&v2);
            pk.w = *reinterpret_cast<uint32_t*>(&v3);
            *reinterpret_cast<uint4*>(bp + i * 16) = pk;
        }
    };

    // -------- accumulators --------------------------------------------------
    float acc[4][8][4];
#pragma unroll
    for (int mt = 0; mt < 4; ++mt)
#pragma unroll
        for (int nt = 0; nt < 8; ++nt)
#pragma unroll
            for (int r = 0; r < 4; ++r) acc[mt][nt][r] = 0.f;

    // lane-dependent ldmatrix base offsets
    const uint32_t a_lane = (warp_m + (lane & 15)) * RSTR + (lane >> 4) * 16;
    const uint32_t b_lane = (warp_n + (lane & 7) + ((lane >> 4) << 3)) * RSTR
                          + ((lane >> 3) & 1) * 16;

    auto compute_tile = [&](int sA, int sB) {
        const uint32_t abase = sb + S_A + sA * STAGE + a_lane;
        const uint32_t bbase = sb + S_B + sB * STAGE + b_lane;
#pragma unroll
        for (int k16 = 0; k16 < 4; ++k16) {
            uint32_t af[4][4];
#pragma unroll
            for (int mt = 0; mt < 4; ++mt)
                LDSM_X4(af[mt][0], af[mt][1], af[mt][2], af[mt][3],
                        abase + mt * 16 * RSTR + k16 * 32);
            uint32_t bf[4][4];
#pragma unroll
            for (int nt2 = 0; nt2 < 4; ++nt2)
                LDSM_X4(bf[nt2][0], bf[nt2][1], bf[nt2][2], bf[nt2][3],
                        bbase + nt2 * 16 * RSTR + k16 * 32);
#pragma unroll
            for (int mt = 0; mt < 4; ++mt)
#pragma unroll
                for (int nt = 0; nt < 8; ++nt) {
                    const int h = (nt & 1) * 2;
                    MMA16816(acc[mt][nt], af[mt], bf[nt >> 1][h], bf[nt >> 1][h + 1]);
                }
        }
    };

    // -------- prologue: A(0),A(1) in flight; B(0) staged --------------------
    issue_a(0, 0); CP_COMMIT();
    issue_a(1, 1); CP_COMMIT();
    ldg_qw(0);
    sts_b(0);
    CP_WAIT1();            // A(0) landed (A(1) may be pending)
    __syncthreads();

    // -------- main loop: exactly one commit per iteration -------------------
    int sA = 0;            // t % 3
    for (int t = 0; t < NT; ++t) {
        const bool more = (t + 1 < NT);
        if (t + 2 < NT) {
            int s2 = sA + 2; if (s2 >= 3) s2 -= 3;
            issue_a(t + 2, s2);
        }
        CP_COMMIT();       // possibly-empty group keeps wait_group 1 exact
        if (more) ldg_qw(t + 1);

        compute_tile(sA, t & 1);

        if (more) {
            sts_b((t + 1) & 1);   // stage last read at t-1, freed by last sync
            CP_WAIT1();           // A(t+1) landed
            __syncthreads();
        }
        if (++sA == 3) sA = 0;
    }

    // -------- epilogue: +bias, fp32 stores ---------------------------------
    const int g  = lane >> 2;
    const int tg = lane & 3;
#pragma unroll
    for (int nt = 0; nt < 8; ++nt) {
        const int c = n0 + warp_n + nt * 8 + tg * 2;
        const float2 bv = *reinterpret_cast<const float2*>(bias + c);
#pragma unroll
        for (int mt = 0; mt < 4; ++mt) {
            const int r0 = m0 + warp_m + mt * 16 + g;
            float2 v0 = make_float2(acc[mt][nt][0] + bv.x, acc[mt][nt][1] + bv.y);
            float2 v1 = make_float2(acc[mt][nt][2] + bv.x, acc[mt][nt][3] + bv.y);
            *reinterpret_cast<float2*>(out + (size_t)r0 * kOutF + c)       = v0;
            *reinterpret_cast<float2*>(out + (size_t)(r0 + 8) * kOutF + c) = v1;
        }
    }
}

// ---------------------------------------------------------------------------
extern "C" void kernel_launch(void* const* d_in, const int* in_sizes, int n_in,
                              void* d_out, int out_size)
{
    (void)in_sizes; (void)n_in; (void)out_size;
    const float* x       = (const float*)d_in[0];
    const float* scales  = (const float*)d_in[1];
    const float* bias    = (const float*)d_in[2];
    const int*   qweight = (const int*)d_in[3];
    const int*   qzeros  = (const int*)d_in[4];
    float*       out     = (float*)d_out;

    const size_t tot8 = (size_t)kM * kInF / 8;
    convert_x_kernel<<<(unsigned)((tot8 + 255) / 256), 256>>>(x);

    cudaFuncSetAttribute(qlinear_hmma_kernel,
                         cudaFuncAttributeMaxDynamicSharedMemorySize, SMEM_TOTAL);
    dim3 grid(kOutF / BN, kM / BM);  // (86, 64)
    qlinear_hmma_kernel<<<grid, 128, SMEM_TOTAL>>>(scales, bias, qweight, qzeros, out);
}